// round 2
// baseline (speedup 1.0000x reference)
#include <cuda_runtime.h>

#define B_    64
#define CIN   512
#define COUT  512
#define HW    784      // 28*28
#define FAN   513      // CIN + 1 (rate column)
#define KSEL  256      // K = COUT * 0.5
#define RATE  0.5f

// Scratch (allocation-free rule: __device__ globals)
__device__ float d_s_scr[B_ * CIN];    // per-(b,c) mean |x|
__device__ float d_g_scr[B_ * COUT];   // gate values after relu

// ---------------------------------------------------------------------------
// Kernel 1: s[b,c] = mean(|x[b,c,:,:]|).  One warp per (b,c) row.
// 102.8 MB streamed -> HBM-bound. float4 loads, 512B/warp-instr, coalesced.
// ---------------------------------------------------------------------------
__global__ void k1_absmean(const float* __restrict__ x) {
    int row  = blockIdx.x * 8 + (threadIdx.x >> 5);   // 32768 rows
    int lane = threadIdx.x & 31;
    const float4* p = reinterpret_cast<const float4*>(x) + (size_t)row * (HW / 4);
    float acc = 0.f;
    #pragma unroll
    for (int i = 0; i < 7; i++) {                      // 196 float4 per row
        int idx = lane + i * 32;
        if (idx < HW / 4) {
            float4 v = p[idx];
            acc += fabsf(v.x) + fabsf(v.y) + fabsf(v.z) + fabsf(v.w);
        }
    }
    #pragma unroll
    for (int o = 16; o; o >>= 1) acc += __shfl_xor_sync(0xffffffffu, acc, o);
    if (lane == 0) d_s_scr[row] = acc * (1.0f / (float)HW);
}

// ---------------------------------------------------------------------------
// Kernel 2: g[b,c] = relu(dot(s_ext[b,:], W[c,:]) + bias[c])
// Grid (16,8): each block = 4 batches x 64 channels. s staged in smem,
// W rows read coalesced (lanes sweep k), 4x4 register accumulators.
// ---------------------------------------------------------------------------
__global__ void k2_gate(const float* __restrict__ W, const float* __restrict__ bias) {
    __shared__ float s_sm[4][FAN + 7];   // stride 520, conflict-free (consecutive-k reads)
    int tid = threadIdx.x;
    int b0  = blockIdx.x * 4;
    int c0  = blockIdx.y * 64;

    for (int idx = tid; idx < 4 * FAN; idx += 512) {
        int bb = idx / FAN, k = idx - bb * FAN;
        s_sm[bb][k] = (k < CIN) ? d_s_scr[(b0 + bb) * CIN + k] : RATE;
    }
    __syncthreads();

    int warp = tid >> 5, lane = tid & 31;
    int cbase = c0 + warp * 4;            // 16 warps x 4 channels = 64 channels
    float acc[4][4];
    #pragma unroll
    for (int bb = 0; bb < 4; bb++)
        #pragma unroll
        for (int cc = 0; cc < 4; cc++) acc[bb][cc] = 0.f;

    const float* w0 = W + (size_t)cbase * FAN;
    for (int k = lane; k < FAN; k += 32) {
        float wv[4], sv[4];
        #pragma unroll
        for (int cc = 0; cc < 4; cc++) wv[cc] = w0[cc * FAN + k];
        #pragma unroll
        for (int bb = 0; bb < 4; bb++) sv[bb] = s_sm[bb][k];
        #pragma unroll
        for (int bb = 0; bb < 4; bb++)
            #pragma unroll
            for (int cc = 0; cc < 4; cc++) acc[bb][cc] += wv[cc] * sv[bb];
    }
    #pragma unroll
    for (int o = 16; o; o >>= 1)
        #pragma unroll
        for (int bb = 0; bb < 4; bb++)
            #pragma unroll
            for (int cc = 0; cc < 4; cc++)
                acc[bb][cc] += __shfl_xor_sync(0xffffffffu, acc[bb][cc], o);

    if (lane == 0) {
        #pragma unroll
        for (int cc = 0; cc < 4; cc++) {
            float bv = bias[cbase + cc];
            #pragma unroll
            for (int bb = 0; bb < 4; bb++)
                d_g_scr[(b0 + bb) * COUT + cbase + cc] = fmaxf(acc[bb][cc] + bv, 0.f);
        }
    }
}

// ---------------------------------------------------------------------------
// Kernel 3: zero the KSEL smallest per row (exact top_k tie-break: strictly
// smaller OR equal-with-lower-index), then renormalize to sum = COUT.
// One block per batch row; smem-broadcast rank loop.
// ---------------------------------------------------------------------------
__global__ void k3_select(float* __restrict__ out) {
    __shared__ float gs[COUT];
    __shared__ float ssum[17];
    int b = blockIdx.x;
    int c = threadIdx.x;
    float gc = d_g_scr[b * COUT + c];
    gs[c] = gc;
    __syncthreads();

    int rank = 0;
    #pragma unroll 8
    for (int j = 0; j < COUT; j++) {
        float v = gs[j];                         // broadcast LDS (all lanes same addr)
        rank += (int)((v < gc) || (v == gc && j < c));
    }
    float t = (rank < KSEL) ? 0.f : gc;

    float sum = t;
    #pragma unroll
    for (int o = 16; o; o >>= 1) sum += __shfl_xor_sync(0xffffffffu, sum, o);
    int warp = c >> 5, lane = c & 31;
    if (lane == 0) ssum[warp] = sum;
    __syncthreads();
    if (c == 0) {
        float tot = 0.f;
        #pragma unroll
        for (int w = 0; w < 16; w++) tot += ssum[w];
        ssum[16] = tot;
    }
    __syncthreads();
    out[b * COUT + c] = t * ((float)COUT / ssum[16]);
}

// ---------------------------------------------------------------------------
extern "C" void kernel_launch(void* const* d_in, const int* in_sizes, int n_in,
                              void* d_out, int out_size) {
    const float* x    = (const float*)d_in[0];
    const float* W    = (const float*)d_in[1];
    const float* bias = (const float*)d_in[2];
    float* out = (float*)d_out;

    k1_absmean<<<(B_ * CIN) / 8, 256>>>(x);
    k2_gate<<<dim3(16, 8), 512>>>(W, bias);
    k3_select<<<B_, 512>>>(out);
}

// round 3
// speedup vs baseline: 1.4700x; 1.4700x over previous
#include <cuda_runtime.h>

#define B_    64
#define CIN   512
#define COUT  512
#define HW    784      // 28*28
#define FAN   513      // CIN + 1 (rate column)
#define KSEL  256      // K = COUT * 0.5
#define RATE  0.5f

// Scratch (allocation-free rule: __device__ globals)
__device__ float d_s_scr[B_ * CIN];    // per-(b,c) mean |x|
__device__ float d_g_scr[B_ * COUT];   // gate values after relu

// ---------------------------------------------------------------------------
// Kernel 1: s[b,c] = mean(|x[b,c,:,:]|).
// One warp per 2 consecutive rows = 392 contiguous float4 (rows are adjacent
// in the flat [B,C,H,W] layout). Fully unrolled 13-iter predicated loop so
// ptxas front-batches the loads (high MLP) -> higher DRAM occupancy.
// ---------------------------------------------------------------------------
__global__ void k1_absmean(const float* __restrict__ x) {
    int w    = blockIdx.x * 8 + (threadIdx.x >> 5);   // 16384 warps, 2 rows each
    int lane = threadIdx.x & 31;
    const float4* p = reinterpret_cast<const float4*>(x) + (size_t)w * 392;

    float a0 = 0.f, a1 = 0.f;
    #pragma unroll
    for (int i = 0; i < 13; i++) {
        int idx = lane + i * 32;
        if (idx < 392) {
            float4 v = p[idx];
            float s = fabsf(v.x) + fabsf(v.y) + fabsf(v.z) + fabsf(v.w);
            if (idx < 196) a0 += s; else a1 += s;
        }
    }
    #pragma unroll
    for (int o = 16; o; o >>= 1) {
        a0 += __shfl_xor_sync(0xffffffffu, a0, o);
        a1 += __shfl_xor_sync(0xffffffffu, a1, o);
    }
    if (lane == 0) {
        d_s_scr[2 * w + 0] = a0 * (1.0f / (float)HW);
        d_s_scr[2 * w + 1] = a1 * (1.0f / (float)HW);
    }
}

// ---------------------------------------------------------------------------
// Kernel 2: g[b,c] = relu(dot(s_ext[b,:], W[c,:]) + bias[c])
// Grid (16,8): each block = 4 batches x 64 channels. s staged in smem,
// W rows read coalesced (lanes sweep k), 4x4 register accumulators.
// ---------------------------------------------------------------------------
__global__ void k2_gate(const float* __restrict__ W, const float* __restrict__ bias) {
    __shared__ float s_sm[4][FAN + 7];   // stride 520, conflict-free
    int tid = threadIdx.x;
    int b0  = blockIdx.x * 4;
    int c0  = blockIdx.y * 64;

    for (int idx = tid; idx < 4 * FAN; idx += 512) {
        int bb = idx / FAN, k = idx - bb * FAN;
        s_sm[bb][k] = (k < CIN) ? d_s_scr[(b0 + bb) * CIN + k] : RATE;
    }
    __syncthreads();

    int warp = tid >> 5, lane = tid & 31;
    int cbase = c0 + warp * 4;            // 16 warps x 4 channels = 64 channels
    float acc[4][4];
    #pragma unroll
    for (int bb = 0; bb < 4; bb++)
        #pragma unroll
        for (int cc = 0; cc < 4; cc++) acc[bb][cc] = 0.f;

    const float* w0 = W + (size_t)cbase * FAN;
    #pragma unroll 4
    for (int k = lane; k < FAN; k += 32) {
        float wv[4], sv[4];
        #pragma unroll
        for (int cc = 0; cc < 4; cc++) wv[cc] = w0[cc * FAN + k];
        #pragma unroll
        for (int bb = 0; bb < 4; bb++) sv[bb] = s_sm[bb][k];
        #pragma unroll
        for (int bb = 0; bb < 4; bb++)
            #pragma unroll
            for (int cc = 0; cc < 4; cc++) acc[bb][cc] += wv[cc] * sv[bb];
    }
    #pragma unroll
    for (int o = 16; o; o >>= 1)
        #pragma unroll
        for (int bb = 0; bb < 4; bb++)
            #pragma unroll
            for (int cc = 0; cc < 4; cc++)
                acc[bb][cc] += __shfl_xor_sync(0xffffffffu, acc[bb][cc], o);

    if (lane == 0) {
        #pragma unroll
        for (int cc = 0; cc < 4; cc++) {
            float bv = bias[cbase + cc];
            #pragma unroll
            for (int bb = 0; bb < 4; bb++)
                d_g_scr[(b0 + bb) * COUT + cbase + cc] = fmaxf(acc[bb][cc] + bv, 0.f);
        }
    }
}

// ---------------------------------------------------------------------------
// Kernel 3: zero the KSEL smallest per row, then renormalize to sum = COUT.
// Radix-select (4 byte passes) for the (KSEL-1)-ranked key; nonneg float bits
// are order-monotone as uint. Ties broken by lowest index (matches top_k;
// the only mass ties are relu zeros, where zeroing is a no-op anyway).
// One block (512 threads) per batch row.
// ---------------------------------------------------------------------------
__global__ void k3_select(float* __restrict__ out) {
    __shared__ unsigned hist[256];
    __shared__ unsigned sh_digit, sh_cumbefore;
    __shared__ unsigned wcnt[16];
    __shared__ float ssum[17];

    int b = blockIdx.x;
    int c = threadIdx.x;
    int warp = c >> 5, lane = c & 31;

    float gc = d_g_scr[b * COUT + c];
    unsigned key = __float_as_uint(gc);      // gc >= 0 -> monotone

    unsigned prefix = 0, mask = 0;
    unsigned target = KSEL - 1;              // remaining rank in candidate set
    unsigned countless = 0;                  // # keys strictly < tau (global)

    #pragma unroll
    for (int shift = 24; shift >= 0; shift -= 8) {
        if (c < 256) hist[c] = 0;
        __syncthreads();
        bool active = ((key & mask) == prefix);
        if (active) atomicAdd(&hist[(key >> shift) & 255u], 1u);
        __syncthreads();

        if (c < 32) {   // warp0: find digit containing 'target'
            unsigned s = 0;
            #pragma unroll
            for (int k = 0; k < 8; k++) s += hist[lane * 8 + k];
            unsigned incl = s;
            #pragma unroll
            for (int o = 1; o < 32; o <<= 1) {
                unsigned t = __shfl_up_sync(0xffffffffu, incl, o);
                if (lane >= o) incl += t;
            }
            unsigned excl = incl - s;
            if (excl <= target && target < incl) {
                unsigned cum = excl;
                unsigned d = lane * 8;
                #pragma unroll
                for (int k = 0; k < 8; k++) {
                    unsigned h = hist[lane * 8 + k];
                    if (cum + h > target) { d = lane * 8 + k; break; }
                    cum += h;
                }
                sh_digit = d;
                sh_cumbefore = cum;
            }
        }
        __syncthreads();
        unsigned cb = sh_cumbefore;
        unsigned dg = sh_digit;
        target    -= cb;
        countless += cb;
        prefix |= dg << shift;
        mask   |= 0xFFu << shift;
        __syncthreads();   // protect hist/sh_* before next round's re-zero
    }

    unsigned tau = prefix;                   // key of (KSEL-1)-ranked element
    unsigned E = KSEL - countless;           // # of tau-equal elements to zero
    bool eq = (key == tau);

    unsigned ball = __ballot_sync(0xffffffffu, eq);
    if (lane == 0) wcnt[warp] = __popc(ball);
    __syncthreads();
    unsigned woff = 0;
    #pragma unroll
    for (int w = 0; w < 16; w++) woff += (w < warp) ? wcnt[w] : 0u;
    unsigned myoff = woff + __popc(ball & ((1u << lane) - 1u));

    bool zero = (key < tau) || (eq && myoff < E);
    float t = zero ? 0.f : gc;

    // block sum + renormalize
    float sum = t;
    #pragma unroll
    for (int o = 16; o; o >>= 1) sum += __shfl_xor_sync(0xffffffffu, sum, o);
    if (lane == 0) ssum[warp] = sum;
    __syncthreads();
    if (c == 0) {
        float tot = 0.f;
        #pragma unroll
        for (int w = 0; w < 16; w++) tot += ssum[w];
        ssum[16] = tot;
    }
    __syncthreads();
    out[b * COUT + c] = t * ((float)COUT / ssum[16]);
}

// ---------------------------------------------------------------------------
extern "C" void kernel_launch(void* const* d_in, const int* in_sizes, int n_in,
                              void* d_out, int out_size) {
    const float* x    = (const float*)d_in[0];
    const float* W    = (const float*)d_in[1];
    const float* bias = (const float*)d_in[2];
    float* out = (float*)d_out;

    k1_absmean<<<2048, 256>>>(x);              // 16384 warps x 2 rows
    k2_gate<<<dim3(16, 8), 512>>>(W, bias);
    k3_select<<<B_, 512>>>(out);
}

// round 4
// speedup vs baseline: 1.6000x; 1.0884x over previous
#include <cuda_runtime.h>

#define B_    64
#define CIN   512
#define COUT  512
#define HW    784      // 28*28
#define FAN   513      // CIN + 1 (rate column)
#define KSEL  256      // K = COUT * 0.5
#define RATE  0.5f

// Scratch (allocation-free rule: __device__ globals)
__device__ float d_s_scr[B_ * CIN];    // per-(b,c) mean |x|
__device__ float d_g_scr[B_ * COUT];   // gate values after relu

// ---------------------------------------------------------------------------
// Kernel 1: s[b,c] = mean(|x[b,c,:,:]|). One warp per row (196 float4),
// R1 config (best measured DRAM util). Early programmatic trigger lets the
// PDL-dependent k2 start its W prologue during k1's last wave.
// ---------------------------------------------------------------------------
__global__ void k1_absmean(const float* __restrict__ x) {
    cudaTriggerProgrammaticLaunchCompletion();
    int row  = blockIdx.x * 8 + (threadIdx.x >> 5);   // 32768 rows
    int lane = threadIdx.x & 31;
    const float4* p = reinterpret_cast<const float4*>(x) + (size_t)row * 196;

    float4 v[6];
    #pragma unroll
    for (int i = 0; i < 6; i++) v[i] = p[lane + 32 * i];
    float4 v6 = make_float4(0.f, 0.f, 0.f, 0.f);
    if (lane < 4) v6 = p[lane + 192];

    float acc = fabsf(v6.x) + fabsf(v6.y) + fabsf(v6.z) + fabsf(v6.w);
    #pragma unroll
    for (int i = 0; i < 6; i++)
        acc += fabsf(v[i].x) + fabsf(v[i].y) + fabsf(v[i].z) + fabsf(v[i].w);

    #pragma unroll
    for (int o = 16; o; o >>= 1) acc += __shfl_xor_sync(0xffffffffu, acc, o);
    if (lane == 0) d_s_scr[row] = acc * (1.0f / (float)HW);
}

// ---------------------------------------------------------------------------
// Kernel 2: g[b,c] = relu(dot(s_ext[b,:], W[c,:]) + bias[c])
// Grid (16,8): block = 4 batches x 64 channels. PDL: stage this block's W
// tile (64x513 floats = 131KB) into dynamic smem BEFORE the grid-dependency
// sync (overlaps k1), then sync, load s, compute entirely from smem.
// ---------------------------------------------------------------------------
#define W_TILE_FLOATS (64 * FAN)            // 32832, divisible by 4
#define S_STRIDE      520
#define K2_SMEM_BYTES ((W_TILE_FLOATS + 4 * S_STRIDE) * 4)

extern __shared__ float k2_smem[];

__global__ void k2_gate(const float* __restrict__ W, const float* __restrict__ bias) {
    float* W_sm = k2_smem;                       // [64][513] flat
    float* s_sm = k2_smem + W_TILE_FLOATS;       // [4][520]
    int tid = threadIdx.x;
    int b0  = blockIdx.x * 4;
    int c0  = blockIdx.y * 64;

    // ---- prologue (independent of k1): stage W tile as float4 ----
    {
        const float4* wsrc = reinterpret_cast<const float4*>(W + (size_t)c0 * FAN);
        float4* wdst = reinterpret_cast<float4*>(W_sm);
        #pragma unroll 4
        for (int i = tid; i < W_TILE_FLOATS / 4; i += 512) wdst[i] = wsrc[i];
    }

    // ---- wait for k1's stores to be visible ----
    cudaGridDependencySynchronize();

    for (int idx = tid; idx < 4 * FAN; idx += 512) {
        int bb = idx / FAN, k = idx - bb * FAN;
        s_sm[bb * S_STRIDE + k] = (k < CIN) ? d_s_scr[(b0 + bb) * CIN + k] : RATE;
    }
    __syncthreads();

    int warp = tid >> 5, lane = tid & 31;
    int cl = warp * 4;                       // channel offset within tile
    float acc[4][4];
    #pragma unroll
    for (int bb = 0; bb < 4; bb++)
        #pragma unroll
        for (int cc = 0; cc < 4; cc++) acc[bb][cc] = 0.f;

    #pragma unroll 4
    for (int k = lane; k < FAN; k += 32) {
        float wv[4], sv[4];
        #pragma unroll
        for (int cc = 0; cc < 4; cc++) wv[cc] = W_sm[(cl + cc) * FAN + k];
        #pragma unroll
        for (int bb = 0; bb < 4; bb++) sv[bb] = s_sm[bb * S_STRIDE + k];
        #pragma unroll
        for (int bb = 0; bb < 4; bb++)
            #pragma unroll
            for (int cc = 0; cc < 4; cc++) acc[bb][cc] += wv[cc] * sv[bb];
    }
    #pragma unroll
    for (int o = 16; o; o >>= 1)
        #pragma unroll
        for (int bb = 0; bb < 4; bb++)
            #pragma unroll
            for (int cc = 0; cc < 4; cc++)
                acc[bb][cc] += __shfl_xor_sync(0xffffffffu, acc[bb][cc], o);

    if (lane == 0) {
        #pragma unroll
        for (int cc = 0; cc < 4; cc++) {
            float bv = bias[c0 + cl + cc];
            #pragma unroll
            for (int bb = 0; bb < 4; bb++)
                d_g_scr[(b0 + bb) * COUT + c0 + cl + cc] = fmaxf(acc[bb][cc] + bv, 0.f);
        }
    }
}

// ---------------------------------------------------------------------------
// Kernel 3: zero the KSEL smallest per row (radix-select, 4 byte passes),
// renormalize to sum = COUT. PDL sync at entry (dispatch overlaps k2).
// ---------------------------------------------------------------------------
__global__ void k3_select(float* __restrict__ out) {
    __shared__ unsigned hist[256];
    __shared__ unsigned sh_digit, sh_cumbefore;
    __shared__ unsigned wcnt[16];
    __shared__ float ssum[17];

    cudaGridDependencySynchronize();

    int b = blockIdx.x;
    int c = threadIdx.x;
    int warp = c >> 5, lane = c & 31;

    float gc = d_g_scr[b * COUT + c];
    unsigned key = __float_as_uint(gc);      // gc >= 0 -> monotone

    unsigned prefix = 0, mask = 0;
    unsigned target = KSEL - 1;              // remaining rank in candidate set
    unsigned countless = 0;                  // # keys strictly < tau (global)

    #pragma unroll
    for (int shift = 24; shift >= 0; shift -= 8) {
        if (c < 256) hist[c] = 0;
        __syncthreads();
        bool active = ((key & mask) == prefix);
        if (active) atomicAdd(&hist[(key >> shift) & 255u], 1u);
        __syncthreads();

        if (c < 32) {   // warp0: find digit containing 'target'
            unsigned s = 0;
            #pragma unroll
            for (int k = 0; k < 8; k++) s += hist[lane * 8 + k];
            unsigned incl = s;
            #pragma unroll
            for (int o = 1; o < 32; o <<= 1) {
                unsigned t = __shfl_up_sync(0xffffffffu, incl, o);
                if (lane >= o) incl += t;
            }
            unsigned excl = incl - s;
            if (excl <= target && target < incl) {
                unsigned cum = excl;
                unsigned d = lane * 8;
                #pragma unroll
                for (int k = 0; k < 8; k++) {
                    unsigned h = hist[lane * 8 + k];
                    if (cum + h > target) { d = lane * 8 + k; break; }
                    cum += h;
                }
                sh_digit = d;
                sh_cumbefore = cum;
            }
        }
        __syncthreads();
        unsigned cb = sh_cumbefore;
        unsigned dg = sh_digit;
        target    -= cb;
        countless += cb;
        prefix |= dg << shift;
        mask   |= 0xFFu << shift;
        __syncthreads();
    }

    unsigned tau = prefix;
    unsigned E = KSEL - countless;           // # tau-equal elements to zero
    bool eq = (key == tau);

    unsigned ball = __ballot_sync(0xffffffffu, eq);
    if (lane == 0) wcnt[warp] = __popc(ball);
    __syncthreads();
    unsigned woff = 0;
    #pragma unroll
    for (int w = 0; w < 16; w++) woff += (w < warp) ? wcnt[w] : 0u;
    unsigned myoff = woff + __popc(ball & ((1u << lane) - 1u));

    bool zero = (key < tau) || (eq && myoff < E);
    float t = zero ? 0.f : gc;

    float sum = t;
    #pragma unroll
    for (int o = 16; o; o >>= 1) sum += __shfl_xor_sync(0xffffffffu, sum, o);
    if (lane == 0) ssum[warp] = sum;
    __syncthreads();
    if (c == 0) {
        float tot = 0.f;
        #pragma unroll
        for (int w = 0; w < 16; w++) tot += ssum[w];
        ssum[16] = tot;
    }
    __syncthreads();
    out[b * COUT + c] = t * ((float)COUT / ssum[16]);
}

// ---------------------------------------------------------------------------
extern "C" void kernel_launch(void* const* d_in, const int* in_sizes, int n_in,
                              void* d_out, int out_size) {
    const float* x    = (const float*)d_in[0];
    const float* W    = (const float*)d_in[1];
    const float* bias = (const float*)d_in[2];
    float* out = (float*)d_out;

    cudaFuncSetAttribute(k2_gate, cudaFuncAttributeMaxDynamicSharedMemorySize,
                         K2_SMEM_BYTES);

    k1_absmean<<<4096, 256>>>(x);

    // k2 with Programmatic Dependent Launch: W-staging prologue overlaps k1.
    {
        cudaLaunchConfig_t cfg = {};
        cfg.gridDim  = dim3(16, 8);
        cfg.blockDim = dim3(512);
        cfg.dynamicSmemBytes = K2_SMEM_BYTES;
        cfg.stream = 0;
        cudaLaunchAttribute at[1];
        at[0].id = cudaLaunchAttributeProgrammaticStreamSerialization;
        at[0].val.programmaticStreamSerializationAllowed = 1;
        cfg.attrs = at;
        cfg.numAttrs = 1;
        cudaLaunchKernelEx(&cfg, k2_gate, W, bias);
    }

    // k3 with PDL: dispatch overlaps k2.
    {
        cudaLaunchConfig_t cfg = {};
        cfg.gridDim  = dim3(B_);
        cfg.blockDim = dim3(512);
        cfg.dynamicSmemBytes = 0;
        cfg.stream = 0;
        cudaLaunchAttribute at[1];
        at[0].id = cudaLaunchAttributeProgrammaticStreamSerialization;
        at[0].val.programmaticStreamSerializationAllowed = 1;
        cfg.attrs = at;
        cfg.numAttrs = 1;
        cudaLaunchKernelEx(&cfg, k3_select, out);
    }
}

// round 5
// speedup vs baseline: 1.6311x; 1.0194x over previous
#include <cuda_runtime.h>

#define B_    64
#define CIN   512
#define COUT  512
#define HW    784      // 28*28
#define FAN   513      // CIN + 1 (rate column)
#define KSEL  256      // K = COUT * 0.5
#define RATE  0.5f

// Scratch (allocation-free rule: __device__ globals)
__device__ float d_s_scr[B_ * CIN];    // per-(b,c) mean |x|
__device__ float d_g_scr[B_ * COUT];   // gate values after relu

// ---------------------------------------------------------------------------
// Kernel 1: s[b,c] = mean(|x[b,c,:,:]|). One warp per row (196 float4),
// R1 config (best measured DRAM util: 5.7 TB/s). __ldcs: data is streamed
// exactly once -> evict-first. Programmatic trigger at the END so the PDL
// dependent (k2) only launches into k1's drain window instead of squatting
// on smem/warp-slots during k1's body (the R3 regression).
// ---------------------------------------------------------------------------
__global__ void k1_absmean(const float* __restrict__ x) {
    int row  = blockIdx.x * 8 + (threadIdx.x >> 5);   // 32768 rows
    int lane = threadIdx.x & 31;
    const float4* p = reinterpret_cast<const float4*>(x) + (size_t)row * 196;
    float acc = 0.f;
    #pragma unroll
    for (int i = 0; i < 7; i++) {                      // 196 float4 per row
        int idx = lane + i * 32;
        if (idx < 196) {
            float4 v = __ldcs(p + idx);
            acc += fabsf(v.x) + fabsf(v.y) + fabsf(v.z) + fabsf(v.w);
        }
    }
    #pragma unroll
    for (int o = 16; o; o >>= 1) acc += __shfl_xor_sync(0xffffffffu, acc, o);
    if (lane == 0) d_s_scr[row] = acc * (1.0f / (float)HW);
    cudaTriggerProgrammaticLaunchCompletion();
}

// ---------------------------------------------------------------------------
// Kernel 2: g[b,c] = relu(dot(s_ext[b,:], W[c,:]) + bias[c])
// Grid (16,8): block = 4 batches x 64 channels. PDL: stage this block's W
// tile (64x513 floats = 131KB) into dynamic smem BEFORE the grid-dependency
// sync (overlaps k1's drain), then sync, load s, compute from smem.
// ---------------------------------------------------------------------------
#define W_TILE_FLOATS (64 * FAN)            // 32832, divisible by 4
#define S_STRIDE      520
#define K2_SMEM_BYTES ((W_TILE_FLOATS + 4 * S_STRIDE) * 4)

extern __shared__ float k2_smem[];

__global__ void k2_gate(const float* __restrict__ W, const float* __restrict__ bias) {
    float* W_sm = k2_smem;                       // [64][513] flat
    float* s_sm = k2_smem + W_TILE_FLOATS;       // [4][520]
    int tid = threadIdx.x;
    int b0  = blockIdx.x * 4;
    int c0  = blockIdx.y * 64;

    // ---- prologue (independent of k1): stage W tile as float4 ----
    {
        const float4* wsrc = reinterpret_cast<const float4*>(W + (size_t)c0 * FAN);
        float4* wdst = reinterpret_cast<float4*>(W_sm);
        #pragma unroll 4
        for (int i = tid; i < W_TILE_FLOATS / 4; i += 512) wdst[i] = wsrc[i];
    }

    // ---- wait for k1's stores to be visible ----
    cudaGridDependencySynchronize();

    for (int idx = tid; idx < 4 * FAN; idx += 512) {
        int bb = idx / FAN, k = idx - bb * FAN;
        s_sm[bb * S_STRIDE + k] = (k < CIN) ? d_s_scr[(b0 + bb) * CIN + k] : RATE;
    }
    __syncthreads();

    int warp = tid >> 5, lane = tid & 31;
    int cl = warp * 4;                       // channel offset within tile
    float acc[4][4];
    #pragma unroll
    for (int bb = 0; bb < 4; bb++)
        #pragma unroll
        for (int cc = 0; cc < 4; cc++) acc[bb][cc] = 0.f;

    #pragma unroll 4
    for (int k = lane; k < FAN; k += 32) {
        float wv[4], sv[4];
        #pragma unroll
        for (int cc = 0; cc < 4; cc++) wv[cc] = W_sm[(cl + cc) * FAN + k];
        #pragma unroll
        for (int bb = 0; bb < 4; bb++) sv[bb] = s_sm[bb * S_STRIDE + k];
        #pragma unroll
        for (int bb = 0; bb < 4; bb++)
            #pragma unroll
            for (int cc = 0; cc < 4; cc++) acc[bb][cc] += wv[cc] * sv[bb];
    }
    #pragma unroll
    for (int o = 16; o; o >>= 1)
        #pragma unroll
        for (int bb = 0; bb < 4; bb++)
            #pragma unroll
            for (int cc = 0; cc < 4; cc++)
                acc[bb][cc] += __shfl_xor_sync(0xffffffffu, acc[bb][cc], o);

    if (lane == 0) {
        #pragma unroll
        for (int cc = 0; cc < 4; cc++) {
            float bv = bias[c0 + cl + cc];
            #pragma unroll
            for (int bb = 0; bb < 4; bb++)
                d_g_scr[(b0 + bb) * COUT + c0 + cl + cc] = fmaxf(acc[bb][cc] + bv, 0.f);
        }
    }
    cudaTriggerProgrammaticLaunchCompletion();
}

// ---------------------------------------------------------------------------
// Kernel 3: zero the KSEL smallest per row (radix-select, 4 byte passes),
// renormalize to sum = COUT. PDL: hist-zero before the grid sync.
// ---------------------------------------------------------------------------
__global__ void k3_select(float* __restrict__ out) {
    __shared__ unsigned hist[256];
    __shared__ unsigned sh_digit, sh_cumbefore;
    __shared__ unsigned wcnt[16];
    __shared__ float ssum[17];

    int b = blockIdx.x;
    int c = threadIdx.x;
    int warp = c >> 5, lane = c & 31;

    if (c < 256) hist[c] = 0;                // overlap-able prologue

    cudaGridDependencySynchronize();

    float gc = d_g_scr[b * COUT + c];
    unsigned key = __float_as_uint(gc);      // gc >= 0 -> monotone

    unsigned prefix = 0, mask = 0;
    unsigned target = KSEL - 1;              // remaining rank in candidate set
    unsigned countless = 0;                  // # keys strictly < tau (global)

    #pragma unroll
    for (int shift = 24; shift >= 0; shift -= 8) {
        if (shift != 24 && c < 256) hist[c] = 0;
        __syncthreads();
        bool active = ((key & mask) == prefix);
        if (active) atomicAdd(&hist[(key >> shift) & 255u], 1u);
        __syncthreads();

        if (c < 32) {   // warp0: find digit containing 'target'
            unsigned s = 0;
            #pragma unroll
            for (int k = 0; k < 8; k++) s += hist[lane * 8 + k];
            unsigned incl = s;
            #pragma unroll
            for (int o = 1; o < 32; o <<= 1) {
                unsigned t = __shfl_up_sync(0xffffffffu, incl, o);
                if (lane >= o) incl += t;
            }
            unsigned excl = incl - s;
            if (excl <= target && target < incl) {
                unsigned cum = excl;
                unsigned d = lane * 8;
                #pragma unroll
                for (int k = 0; k < 8; k++) {
                    unsigned h = hist[lane * 8 + k];
                    if (cum + h > target) { d = lane * 8 + k; break; }
                    cum += h;
                }
                sh_digit = d;
                sh_cumbefore = cum;
            }
        }
        __syncthreads();
        unsigned cb = sh_cumbefore;
        unsigned dg = sh_digit;
        target    -= cb;
        countless += cb;
        prefix |= dg << shift;
        mask   |= 0xFFu << shift;
        __syncthreads();
    }

    unsigned tau = prefix;
    unsigned E = KSEL - countless;           // # tau-equal elements to zero
    bool eq = (key == tau);

    unsigned ball = __ballot_sync(0xffffffffu, eq);
    if (lane == 0) wcnt[warp] = __popc(ball);
    __syncthreads();
    unsigned woff = 0;
    #pragma unroll
    for (int w = 0; w < 16; w++) woff += (w < warp) ? wcnt[w] : 0u;
    unsigned myoff = woff + __popc(ball & ((1u << lane) - 1u));

    bool zero = (key < tau) || (eq && myoff < E);
    float t = zero ? 0.f : gc;

    float sum = t;
    #pragma unroll
    for (int o = 16; o; o >>= 1) sum += __shfl_xor_sync(0xffffffffu, sum, o);
    if (lane == 0) ssum[warp] = sum;
    __syncthreads();
    if (c == 0) {
        float tot = 0.f;
        #pragma unroll
        for (int w = 0; w < 16; w++) tot += ssum[w];
        ssum[16] = tot;
    }
    __syncthreads();
    out[b * COUT + c] = t * ((float)COUT / ssum[16]);
}

// ---------------------------------------------------------------------------
extern "C" void kernel_launch(void* const* d_in, const int* in_sizes, int n_in,
                              void* d_out, int out_size) {
    const float* x    = (const float*)d_in[0];
    const float* W    = (const float*)d_in[1];
    const float* bias = (const float*)d_in[2];
    float* out = (float*)d_out;

    cudaFuncSetAttribute(k2_gate, cudaFuncAttributeMaxDynamicSharedMemorySize,
                         K2_SMEM_BYTES);

    k1_absmean<<<4096, 256>>>(x);

    // k2 with Programmatic Dependent Launch (launches into k1's drain window)
    {
        cudaLaunchConfig_t cfg = {};
        cfg.gridDim  = dim3(16, 8);
        cfg.blockDim = dim3(512);
        cfg.dynamicSmemBytes = K2_SMEM_BYTES;
        cfg.stream = 0;
        cudaLaunchAttribute at[1];
        at[0].id = cudaLaunchAttributeProgrammaticStreamSerialization;
        at[0].val.programmaticStreamSerializationAllowed = 1;
        cfg.attrs = at;
        cfg.numAttrs = 1;
        cudaLaunchKernelEx(&cfg, k2_gate, W, bias);
    }

    // k3 with PDL: dispatch overlaps k2's tail.
    {
        cudaLaunchConfig_t cfg = {};
        cfg.gridDim  = dim3(B_);
        cfg.blockDim = dim3(512);
        cfg.dynamicSmemBytes = 0;
        cfg.stream = 0;
        cudaLaunchAttribute at[1];
        at[0].id = cudaLaunchAttributeProgrammaticStreamSerialization;
        at[0].val.programmaticStreamSerializationAllowed = 1;
        cfg.attrs = at;
        cfg.numAttrs = 1;
        cudaLaunchKernelEx(&cfg, k3_select, out);
    }
}

// round 6
// speedup vs baseline: 1.7927x; 1.0991x over previous
#include <cuda_runtime.h>

#define B_    64
#define CIN   512
#define COUT  512
#define HW    784      // 28*28
#define FAN   513      // CIN + 1 (rate column)
#define KSEL  256      // K = COUT * 0.5
#define RATE  0.5f

#define K1_BLOCKS 592                  // 148 SMs x 4 blocks -> single wave
#define K1_WARPS  (K1_BLOCKS * 8)      // 4736 warps
#define NROWS     (B_ * CIN)           // 32768

// Scratch (allocation-free rule: __device__ globals)
__device__ float d_s_scr[B_ * CIN];    // per-(b,c) mean |x|
__device__ float d_g_scr[B_ * COUT];   // gate values after relu

// ---------------------------------------------------------------------------
// Kernel 1: s[b,c] = mean(|x[b,c,:,:]|).
// Persistent single-wave grid (592 blocks = 148x4, occupancy pinned by
// __launch_bounds__). Each warp loops over rows with stride 2*K1_WARPS,
// processing TWO rows per body (interleaved loads -> per-thread MLP ~12,
// reduction stalls amortized). Eliminates the ~3 wave transitions of the
// 4096-block layout.
// ---------------------------------------------------------------------------
__global__ void __launch_bounds__(256, 4) k1_absmean(const float* __restrict__ x) {
    int w    = blockIdx.x * 8 + (threadIdx.x >> 5);
    int lane = threadIdx.x & 31;
    const float4* xb = reinterpret_cast<const float4*>(x);

    for (int r0 = w; r0 < NROWS; r0 += 2 * K1_WARPS) {
        int r1 = r0 + K1_WARPS;
        bool has1 = (r1 < NROWS);
        const float4* p0 = xb + (size_t)r0 * 196;
        const float4* p1 = xb + (size_t)r1 * 196;

        float a0 = 0.f, a1 = 0.f;
        #pragma unroll
        for (int i = 0; i < 7; i++) {
            int idx = lane + i * 32;
            bool in = (idx < 196);
            float4 v0 = make_float4(0.f, 0.f, 0.f, 0.f);
            float4 v1 = make_float4(0.f, 0.f, 0.f, 0.f);
            if (in)          v0 = p0[idx];
            if (in && has1)  v1 = p1[idx];
            a0 += fabsf(v0.x) + fabsf(v0.y) + fabsf(v0.z) + fabsf(v0.w);
            a1 += fabsf(v1.x) + fabsf(v1.y) + fabsf(v1.z) + fabsf(v1.w);
        }
        #pragma unroll
        for (int o = 16; o; o >>= 1) {
            a0 += __shfl_xor_sync(0xffffffffu, a0, o);
            a1 += __shfl_xor_sync(0xffffffffu, a1, o);
        }
        if (lane == 0) {
            d_s_scr[r0] = a0 * (1.0f / (float)HW);
            if (has1) d_s_scr[r1] = a1 * (1.0f / (float)HW);
        }
    }
    cudaTriggerProgrammaticLaunchCompletion();
}

// ---------------------------------------------------------------------------
// Kernel 2: g[b,c] = relu(dot(s_ext[b,:], W[c,:]) + bias[c])
// Grid (16,8): block = 4 batches x 64 channels. PDL: stage this block's W
// tile (64x513 floats = 131KB) into dynamic smem BEFORE the grid-dependency
// sync (overlaps k1's drain), then sync, load s, compute from smem.
// ---------------------------------------------------------------------------
#define W_TILE_FLOATS (64 * FAN)            // 32832, divisible by 4
#define S_STRIDE      520
#define K2_SMEM_BYTES ((W_TILE_FLOATS + 4 * S_STRIDE) * 4)

extern __shared__ float k2_smem[];

__global__ void k2_gate(const float* __restrict__ W, const float* __restrict__ bias) {
    float* W_sm = k2_smem;                       // [64][513] flat
    float* s_sm = k2_smem + W_TILE_FLOATS;       // [4][520]
    int tid = threadIdx.x;
    int b0  = blockIdx.x * 4;
    int c0  = blockIdx.y * 64;

    // ---- prologue (independent of k1): stage W tile as float4 ----
    {
        const float4* wsrc = reinterpret_cast<const float4*>(W + (size_t)c0 * FAN);
        float4* wdst = reinterpret_cast<float4*>(W_sm);
        #pragma unroll 4
        for (int i = tid; i < W_TILE_FLOATS / 4; i += 512) wdst[i] = wsrc[i];
    }

    // ---- wait for k1's stores to be visible ----
    cudaGridDependencySynchronize();

    for (int idx = tid; idx < 4 * FAN; idx += 512) {
        int bb = idx / FAN, k = idx - bb * FAN;
        s_sm[bb * S_STRIDE + k] = (k < CIN) ? d_s_scr[(b0 + bb) * CIN + k] : RATE;
    }
    __syncthreads();

    int warp = tid >> 5, lane = tid & 31;
    int cl = warp * 4;                       // channel offset within tile
    float acc[4][4];
    #pragma unroll
    for (int bb = 0; bb < 4; bb++)
        #pragma unroll
        for (int cc = 0; cc < 4; cc++) acc[bb][cc] = 0.f;

    #pragma unroll 4
    for (int k = lane; k < FAN; k += 32) {
        float wv[4], sv[4];
        #pragma unroll
        for (int cc = 0; cc < 4; cc++) wv[cc] = W_sm[(cl + cc) * FAN + k];
        #pragma unroll
        for (int bb = 0; bb < 4; bb++) sv[bb] = s_sm[bb * S_STRIDE + k];
        #pragma unroll
        for (int bb = 0; bb < 4; bb++)
            #pragma unroll
            for (int cc = 0; cc < 4; cc++) acc[bb][cc] += wv[cc] * sv[bb];
    }
    #pragma unroll
    for (int o = 16; o; o >>= 1)
        #pragma unroll
        for (int bb = 0; bb < 4; bb++)
            #pragma unroll
            for (int cc = 0; cc < 4; cc++)
                acc[bb][cc] += __shfl_xor_sync(0xffffffffu, acc[bb][cc], o);

    if (lane == 0) {
        #pragma unroll
        for (int cc = 0; cc < 4; cc++) {
            float bv = bias[c0 + cl + cc];
            #pragma unroll
            for (int bb = 0; bb < 4; bb++)
                d_g_scr[(b0 + bb) * COUT + c0 + cl + cc] = fmaxf(acc[bb][cc] + bv, 0.f);
        }
    }
    cudaTriggerProgrammaticLaunchCompletion();
}

// ---------------------------------------------------------------------------
// Kernel 3: zero the KSEL smallest per row (radix-select, 4 byte passes),
// renormalize to sum = COUT. PDL: hist-zero before the grid sync.
// ---------------------------------------------------------------------------
__global__ void k3_select(float* __restrict__ out) {
    __shared__ unsigned hist[256];
    __shared__ unsigned sh_digit, sh_cumbefore;
    __shared__ unsigned wcnt[16];
    __shared__ float ssum[17];

    int b = blockIdx.x;
    int c = threadIdx.x;
    int warp = c >> 5, lane = c & 31;

    if (c < 256) hist[c] = 0;                // overlap-able prologue

    cudaGridDependencySynchronize();

    float gc = d_g_scr[b * COUT + c];
    unsigned key = __float_as_uint(gc);      // gc >= 0 -> monotone

    unsigned prefix = 0, mask = 0;
    unsigned target = KSEL - 1;              // remaining rank in candidate set
    unsigned countless = 0;                  // # keys strictly < tau (global)

    #pragma unroll
    for (int shift = 24; shift >= 0; shift -= 8) {
        if (shift != 24 && c < 256) hist[c] = 0;
        __syncthreads();
        bool active = ((key & mask) == prefix);
        if (active) atomicAdd(&hist[(key >> shift) & 255u], 1u);
        __syncthreads();

        if (c < 32) {   // warp0: find digit containing 'target'
            unsigned s = 0;
            #pragma unroll
            for (int k = 0; k < 8; k++) s += hist[lane * 8 + k];
            unsigned incl = s;
            #pragma unroll
            for (int o = 1; o < 32; o <<= 1) {
                unsigned t = __shfl_up_sync(0xffffffffu, incl, o);
                if (lane >= o) incl += t;
            }
            unsigned excl = incl - s;
            if (excl <= target && target < incl) {
                unsigned cum = excl;
                unsigned d = lane * 8;
                #pragma unroll
                for (int k = 0; k < 8; k++) {
                    unsigned h = hist[lane * 8 + k];
                    if (cum + h > target) { d = lane * 8 + k; break; }
                    cum += h;
                }
                sh_digit = d;
                sh_cumbefore = cum;
            }
        }
        __syncthreads();
        unsigned cb = sh_cumbefore;
        unsigned dg = sh_digit;
        target    -= cb;
        countless += cb;
        prefix |= dg << shift;
        mask   |= 0xFFu << shift;
        __syncthreads();
    }

    unsigned tau = prefix;
    unsigned E = KSEL - countless;           // # tau-equal elements to zero
    bool eq = (key == tau);

    unsigned ball = __ballot_sync(0xffffffffu, eq);
    if (lane == 0) wcnt[warp] = __popc(ball);
    __syncthreads();
    unsigned woff = 0;
    #pragma unroll
    for (int w = 0; w < 16; w++) woff += (w < warp) ? wcnt[w] : 0u;
    unsigned myoff = woff + __popc(ball & ((1u << lane) - 1u));

    bool zero = (key < tau) || (eq && myoff < E);
    float t = zero ? 0.f : gc;

    float sum = t;
    #pragma unroll
    for (int o = 16; o; o >>= 1) sum += __shfl_xor_sync(0xffffffffu, sum, o);
    if (lane == 0) ssum[warp] = sum;
    __syncthreads();
    if (c == 0) {
        float tot = 0.f;
        #pragma unroll
        for (int w = 0; w < 16; w++) tot += ssum[w];
        ssum[16] = tot;
    }
    __syncthreads();
    out[b * COUT + c] = t * ((float)COUT / ssum[16]);
}

// ---------------------------------------------------------------------------
extern "C" void kernel_launch(void* const* d_in, const int* in_sizes, int n_in,
                              void* d_out, int out_size) {
    const float* x    = (const float*)d_in[0];
    const float* W    = (const float*)d_in[1];
    const float* bias = (const float*)d_in[2];
    float* out = (float*)d_out;

    cudaFuncSetAttribute(k2_gate, cudaFuncAttributeMaxDynamicSharedMemorySize,
                         K2_SMEM_BYTES);

    k1_absmean<<<K1_BLOCKS, 256>>>(x);

    // k2 with Programmatic Dependent Launch (launches into k1's drain window)
    {
        cudaLaunchConfig_t cfg = {};
        cfg.gridDim  = dim3(16, 8);
        cfg.blockDim = dim3(512);
        cfg.dynamicSmemBytes = K2_SMEM_BYTES;
        cfg.stream = 0;
        cudaLaunchAttribute at[1];
        at[0].id = cudaLaunchAttributeProgrammaticStreamSerialization;
        at[0].val.programmaticStreamSerializationAllowed = 1;
        cfg.attrs = at;
        cfg.numAttrs = 1;
        cudaLaunchKernelEx(&cfg, k2_gate, W, bias);
    }

    // k3 with PDL: dispatch overlaps k2's tail.
    {
        cudaLaunchConfig_t cfg = {};
        cfg.gridDim  = dim3(B_);
        cfg.blockDim = dim3(512);
        cfg.dynamicSmemBytes = 0;
        cfg.stream = 0;
        cudaLaunchAttribute at[1];
        at[0].id = cudaLaunchAttributeProgrammaticStreamSerialization;
        at[0].val.programmaticStreamSerializationAllowed = 1;
        cfg.attrs = at;
        cfg.numAttrs = 1;
        cudaLaunchKernelEx(&cfg, k3_select, out);
    }
}

// round 7
// speedup vs baseline: 1.7954x; 1.0015x over previous
#include <cuda_runtime.h>

#define B_    64
#define CIN   512
#define COUT  512
#define HW    784      // 28*28
#define FAN   513      // CIN + 1 (rate column)
#define KSEL  256      // K = COUT * 0.5
#define RATE  0.5f

#define K1_BLOCKS 888                  // 148 SMs x 6 resident blocks
#define K1_WARPS  (K1_BLOCKS * 8)      // 7104 warps
#define NROWS     (B_ * CIN)           // 32768

// Scratch (allocation-free rule: __device__ globals)
__device__ float d_s_scr[B_ * CIN];    // per-(b,c) mean |x|
__device__ float d_g_scr[B_ * COUT];   // gate values after relu

// ---------------------------------------------------------------------------
// Kernel 1: s[b,c] = mean(|x[b,c,:,:]|).
// Persistent grid (888 blocks, occ pinned to 6 blocks/SM -> 42-reg budget,
// proven body needs 36). Grid-stride loop, ONE row per iteration: the simple
// 7x predicated float4 body that measured best (18.6us / 72% DRAM in R1).
// Persistent layout kept for its staggered drain -> PDL dependents overlap
// (measured 0.7us exposed in R5 vs 3.6us with multi-wave grids).
// ---------------------------------------------------------------------------
__global__ void __launch_bounds__(256, 6) k1_absmean(const float* __restrict__ x) {
    int w    = blockIdx.x * 8 + (threadIdx.x >> 5);
    int lane = threadIdx.x & 31;
    const float4* xb = reinterpret_cast<const float4*>(x);

    for (int row = w; row < NROWS; row += K1_WARPS) {
        const float4* p = xb + (size_t)row * 196;
        float acc = 0.f;
        #pragma unroll
        for (int i = 0; i < 7; i++) {
            int idx = lane + i * 32;
            if (idx < 196) {
                float4 v = p[idx];
                acc += fabsf(v.x) + fabsf(v.y) + fabsf(v.z) + fabsf(v.w);
            }
        }
        #pragma unroll
        for (int o = 16; o; o >>= 1) acc += __shfl_xor_sync(0xffffffffu, acc, o);
        if (lane == 0) d_s_scr[row] = acc * (1.0f / (float)HW);
    }
    cudaTriggerProgrammaticLaunchCompletion();
}

// ---------------------------------------------------------------------------
// Kernel 2: g[b,c] = relu(dot(s_ext[b,:], W[c,:]) + bias[c])
// Grid (16,8): block = 4 batches x 64 channels. PDL: stage this block's W
// tile (64x513 floats = 131KB) into dynamic smem BEFORE the grid-dependency
// sync (overlaps k1's drain), then sync, load s, compute from smem.
// ---------------------------------------------------------------------------
#define W_TILE_FLOATS (64 * FAN)            // 32832, divisible by 4
#define S_STRIDE      520
#define K2_SMEM_BYTES ((W_TILE_FLOATS + 4 * S_STRIDE) * 4)

extern __shared__ float k2_smem[];

__global__ void k2_gate(const float* __restrict__ W, const float* __restrict__ bias) {
    float* W_sm = k2_smem;                       // [64][513] flat
    float* s_sm = k2_smem + W_TILE_FLOATS;       // [4][520]
    int tid = threadIdx.x;
    int b0  = blockIdx.x * 4;
    int c0  = blockIdx.y * 64;

    // ---- prologue (independent of k1): stage W tile as float4 ----
    {
        const float4* wsrc = reinterpret_cast<const float4*>(W + (size_t)c0 * FAN);
        float4* wdst = reinterpret_cast<float4*>(W_sm);
        #pragma unroll 4
        for (int i = tid; i < W_TILE_FLOATS / 4; i += 512) wdst[i] = wsrc[i];
    }

    // ---- wait for k1's stores to be visible ----
    cudaGridDependencySynchronize();

    for (int idx = tid; idx < 4 * FAN; idx += 512) {
        int bb = idx / FAN, k = idx - bb * FAN;
        s_sm[bb * S_STRIDE + k] = (k < CIN) ? d_s_scr[(b0 + bb) * CIN + k] : RATE;
    }
    __syncthreads();

    int warp = tid >> 5, lane = tid & 31;
    int cl = warp * 4;                       // channel offset within tile
    float acc[4][4];
    #pragma unroll
    for (int bb = 0; bb < 4; bb++)
        #pragma unroll
        for (int cc = 0; cc < 4; cc++) acc[bb][cc] = 0.f;

    #pragma unroll 4
    for (int k = lane; k < FAN; k += 32) {
        float wv[4], sv[4];
        #pragma unroll
        for (int cc = 0; cc < 4; cc++) wv[cc] = W_sm[(cl + cc) * FAN + k];
        #pragma unroll
        for (int bb = 0; bb < 4; bb++) sv[bb] = s_sm[bb * S_STRIDE + k];
        #pragma unroll
        for (int bb = 0; bb < 4; bb++)
            #pragma unroll
            for (int cc = 0; cc < 4; cc++) acc[bb][cc] += wv[cc] * sv[bb];
    }
    #pragma unroll
    for (int o = 16; o; o >>= 1)
        #pragma unroll
        for (int bb = 0; bb < 4; bb++)
            #pragma unroll
            for (int cc = 0; cc < 4; cc++)
                acc[bb][cc] += __shfl_xor_sync(0xffffffffu, acc[bb][cc], o);

    if (lane == 0) {
        #pragma unroll
        for (int cc = 0; cc < 4; cc++) {
            float bv = bias[c0 + cl + cc];
            #pragma unroll
            for (int bb = 0; bb < 4; bb++)
                d_g_scr[(b0 + bb) * COUT + c0 + cl + cc] = fmaxf(acc[bb][cc] + bv, 0.f);
        }
    }
    cudaTriggerProgrammaticLaunchCompletion();
}

// ---------------------------------------------------------------------------
// Kernel 3: zero the KSEL smallest per row (radix-select, 4 byte passes),
// renormalize to sum = COUT. PDL: hist-zero before the grid sync.
// ---------------------------------------------------------------------------
__global__ void k3_select(float* __restrict__ out) {
    __shared__ unsigned hist[256];
    __shared__ unsigned sh_digit, sh_cumbefore;
    __shared__ unsigned wcnt[16];
    __shared__ float ssum[17];

    int b = blockIdx.x;
    int c = threadIdx.x;
    int warp = c >> 5, lane = c & 31;

    if (c < 256) hist[c] = 0;                // overlap-able prologue

    cudaGridDependencySynchronize();

    float gc = d_g_scr[b * COUT + c];
    unsigned key = __float_as_uint(gc);      // gc >= 0 -> monotone

    unsigned prefix = 0, mask = 0;
    unsigned target = KSEL - 1;              // remaining rank in candidate set
    unsigned countless = 0;                  // # keys strictly < tau (global)

    #pragma unroll
    for (int shift = 24; shift >= 0; shift -= 8) {
        if (shift != 24 && c < 256) hist[c] = 0;
        __syncthreads();
        bool active = ((key & mask) == prefix);
        if (active) atomicAdd(&hist[(key >> shift) & 255u], 1u);
        __syncthreads();

        if (c < 32) {   // warp0: find digit containing 'target'
            unsigned s = 0;
            #pragma unroll
            for (int k = 0; k < 8; k++) s += hist[lane * 8 + k];
            unsigned incl = s;
            #pragma unroll
            for (int o = 1; o < 32; o <<= 1) {
                unsigned t = __shfl_up_sync(0xffffffffu, incl, o);
                if (lane >= o) incl += t;
            }
            unsigned excl = incl - s;
            if (excl <= target && target < incl) {
                unsigned cum = excl;
                unsigned d = lane * 8;
                #pragma unroll
                for (int k = 0; k < 8; k++) {
                    unsigned h = hist[lane * 8 + k];
                    if (cum + h > target) { d = lane * 8 + k; break; }
                    cum += h;
                }
                sh_digit = d;
                sh_cumbefore = cum;
            }
        }
        __syncthreads();
        unsigned cb = sh_cumbefore;
        unsigned dg = sh_digit;
        target    -= cb;
        countless += cb;
        prefix |= dg << shift;
        mask   |= 0xFFu << shift;
        __syncthreads();
    }

    unsigned tau = prefix;
    unsigned E = KSEL - countless;           // # tau-equal elements to zero
    bool eq = (key == tau);

    unsigned ball = __ballot_sync(0xffffffffu, eq);
    if (lane == 0) wcnt[warp] = __popc(ball);
    __syncthreads();
    unsigned woff = 0;
    #pragma unroll
    for (int w = 0; w < 16; w++) woff += (w < warp) ? wcnt[w] : 0u;
    unsigned myoff = woff + __popc(ball & ((1u << lane) - 1u));

    bool zero = (key < tau) || (eq && myoff < E);
    float t = zero ? 0.f : gc;

    float sum = t;
    #pragma unroll
    for (int o = 16; o; o >>= 1) sum += __shfl_xor_sync(0xffffffffu, sum, o);
    if (lane == 0) ssum[warp] = sum;
    __syncthreads();
    if (c == 0) {
        float tot = 0.f;
        #pragma unroll
        for (int w = 0; w < 16; w++) tot += ssum[w];
        ssum[16] = tot;
    }
    __syncthreads();
    out[b * COUT + c] = t * ((float)COUT / ssum[16]);
}

// ---------------------------------------------------------------------------
extern "C" void kernel_launch(void* const* d_in, const int* in_sizes, int n_in,
                              void* d_out, int out_size) {
    const float* x    = (const float*)d_in[0];
    const float* W    = (const float*)d_in[1];
    const float* bias = (const float*)d_in[2];
    float* out = (float*)d_out;

    cudaFuncSetAttribute(k2_gate, cudaFuncAttributeMaxDynamicSharedMemorySize,
                         K2_SMEM_BYTES);

    k1_absmean<<<K1_BLOCKS, 256>>>(x);

    // k2 with Programmatic Dependent Launch (launches into k1's drain window)
    {
        cudaLaunchConfig_t cfg = {};
        cfg.gridDim  = dim3(16, 8);
        cfg.blockDim = dim3(512);
        cfg.dynamicSmemBytes = K2_SMEM_BYTES;
        cfg.stream = 0;
        cudaLaunchAttribute at[1];
        at[0].id = cudaLaunchAttributeProgrammaticStreamSerialization;
        at[0].val.programmaticStreamSerializationAllowed = 1;
        cfg.attrs = at;
        cfg.numAttrs = 1;
        cudaLaunchKernelEx(&cfg, k2_gate, W, bias);
    }

    // k3 with PDL: dispatch overlaps k2's tail.
    {
        cudaLaunchConfig_t cfg = {};
        cfg.gridDim  = dim3(B_);
        cfg.blockDim = dim3(512);
        cfg.dynamicSmemBytes = 0;
        cfg.stream = 0;
        cudaLaunchAttribute at[1];
        at[0].id = cudaLaunchAttributeProgrammaticStreamSerialization;
        at[0].val.programmaticStreamSerializationAllowed = 1;
        cfg.attrs = at;
        cfg.numAttrs = 1;
        cudaLaunchKernelEx(&cfg, k3_select, out);
    }
}